// round 4
// baseline (speedup 1.0000x reference)
#include <cuda_runtime.h>
#include <math.h>

#define DEPTH 2
#define NQ 4
#define M_CH 512
#define B_SZ 128
#define NGRP 8            // row-groups per image (4 rows each)

// Precomputed Rot gates: [layer][qubit][m][8]
__device__ float g_gates[DEPTH * NQ * M_CH * 8];
// Pooling partials: [b][grp][side(0=L,1=R)][m]  -> 128*8*2*512 floats = 4 MB
__device__ float g_part[B_SZ * NGRP * 2 * M_CH];

__global__ void gates_kernel(const float* __restrict__ w) {
    int t = blockIdx.x * blockDim.x + threadIdx.x;   // 0 .. 4095
    if (t >= DEPTH * NQ * M_CH) return;
    int m     = t & (M_CH - 1);
    int q     = (t >> 9) & 3;
    int layer = t >> 11;
    const float* wp = w + m * (DEPTH * NQ * 3) + layer * (NQ * 3) + q * 3;
    float phi = wp[0], theta = wp[1], omega = wp[2];
    float st, ct; sincosf(0.5f * theta,         &st, &ct);
    float sp, cp; sincosf(0.5f * (phi + omega), &sp, &cp);
    float sm, cm; sincosf(0.5f * (phi - omega), &sm, &cm);
    float* g = g_gates + (size_t)t * 8;
    g[0] =  cp * ct;  g[1] = -sp * ct;
    g[2] = -cm * st;  g[3] = -sm * st;
    g[4] =  cm * st;  g[5] = -sm * st;
    g[6] =  cp * ct;  g[7] =  sp * ct;
}

// ---- Kernel P: streaming pooling partials. One CTA = (b, rowgroup of 4 rows). ----
__global__ __launch_bounds__(512, 3) void pool_kernel(const float* __restrict__ in) {
    const int bid = blockIdx.x;            // 0..1023
    const int b   = bid >> 3;
    const int grp = bid & (NGRP - 1);
    const int m   = threadIdx.x;

    const float* base = in + (size_t)b * (32 * 32 * M_CH)
                           + (size_t)grp * (4 * 32 * M_CH) + m;
    float sL = 0.f, sR = 0.f;
    #pragma unroll
    for (int r = 0; r < 4; r++) {
        const float* row = base + (size_t)r * (32 * M_CH);
        #pragma unroll
        for (int c = 0; c < 16; c++)  sL += __ldg(row + c * M_CH);
        #pragma unroll
        for (int c = 16; c < 32; c++) sR += __ldg(row + c * M_CH);
    }
    float* p = g_part + (size_t)bid * (2 * M_CH);
    p[m]        = sL;
    p[M_CH + m] = sR;
}

// ---- Kernel S: reduce partials (L2-hot) + 4-qubit sim ----
__global__ __launch_bounds__(512) void sim_kernel(float* __restrict__ out) {
    const int b = blockIdx.x;
    const int m = threadIdx.x;

    const float* p = g_part + (size_t)b * (NGRP * 2 * M_CH) + m;
    float a00 = 0.f, a01 = 0.f, a10 = 0.f, a11 = 0.f;
    #pragma unroll
    for (int g = 0; g < 4; g++) {
        a00 += p[g * 2 * M_CH];
        a01 += p[g * 2 * M_CH + M_CH];
    }
    #pragma unroll
    for (int g = 4; g < 8; g++) {
        a10 += p[g * 2 * M_CH];
        a11 += p[g * 2 * M_CH + M_CH];
    }

    const float PI = 3.14159265358979f;
    const float inv = 1.f / 256.f;
    float ang0 = tanhf(a00 * inv) * PI;
    float ang1 = tanhf(a01 * inv) * PI;
    float ang2 = tanhf(a10 * inv) * PI;
    float ang3 = tanhf(a11 * inv) * PI;

    float s0, c0, s1, c1, s2, c2, s3, c3;
    sincosf(0.5f * ang0, &s0, &c0);
    sincosf(0.5f * ang1, &s1, &c1);
    sincosf(0.5f * ang2, &s2, &c2);
    sincosf(0.5f * ang3, &s3, &c3);

    float re[16], im[16];
    {
        float p0[2] = {c0, s0}, p1[2] = {c1, s1}, p2[2] = {c2, s2}, p3[2] = {c3, s3};
        #pragma unroll
        for (int x = 0; x < 16; x++) {
            re[x] = p0[(x >> 3) & 1] * p1[(x >> 2) & 1] * p2[(x >> 1) & 1] * p3[x & 1];
            im[x] = 0.f;
        }
    }

    // 6-CNOT cascade composed: (a,b,c,d) -> (a, a^b, b^c, c^d); new[PERM[x]] = old[x]
    const int PERM[16] = {0, 1, 3, 2, 6, 7, 5, 4, 12, 13, 15, 14, 10, 11, 9, 8};

    #pragma unroll
    for (int layer = 0; layer < DEPTH; layer++) {
        #pragma unroll
        for (int q = 0; q < NQ; q++) {
            const float4* gp =
                (const float4*)(g_gates + ((size_t)((layer * NQ + q) * M_CH + m)) * 8);
            float4 gA = gp[0];
            float4 gB = gp[1];
            const int mask = 8 >> q;
            #pragma unroll
            for (int i = 0; i < 16; i++) {
                if (i & mask) continue;
                const int j = i | mask;
                float ar = re[i], ai = im[i], br = re[j], bi = im[j];
                re[i] = gA.x * ar - gA.y * ai + gA.z * br - gA.w * bi;
                im[i] = gA.x * ai + gA.y * ar + gA.z * bi + gA.w * br;
                re[j] = gB.x * ar - gB.y * ai + gB.z * br - gB.w * bi;
                im[j] = gB.x * ai + gB.y * ar + gB.z * bi + gB.w * br;
            }
        }
        float tr[16], ti[16];
        #pragma unroll
        for (int x = 0; x < 16; x++) { tr[PERM[x]] = re[x]; ti[PERM[x]] = im[x]; }
        #pragma unroll
        for (int x = 0; x < 16; x++) { re[x] = tr[x]; im[x] = ti[x]; }
    }

    float z = 0.f;
    #pragma unroll
    for (int x = 0; x < 8; x++)  z += re[x] * re[x] + im[x] * im[x];
    #pragma unroll
    for (int x = 8; x < 16; x++) z -= re[x] * re[x] + im[x] * im[x];

    out[(size_t)b * M_CH + m] = z;
}

extern "C" void kernel_launch(void* const* d_in, const int* in_sizes, int n_in,
                              void* d_out, int out_size) {
    const float* in = (const float*)d_in[0];
    const float* w  = (const float*)d_in[1];
    if (n_in >= 2 && in_sizes[0] < in_sizes[1]) {
        const float* t = in; in = w; w = t;
    }
    gates_kernel<<<16, 256>>>(w);
    pool_kernel<<<B_SZ * NGRP, 512>>>(in);
    sim_kernel<<<B_SZ, 512>>>((float*)d_out);
}

// round 5
// speedup vs baseline: 1.0538x; 1.0538x over previous
#include <cuda_runtime.h>
#include <math.h>

#define DEPTH 2
#define NQ 4
#define M_CH 512
#define B_SZ 128
#define NSLICE 16          // 2-row slices per image
#define NGATE (DEPTH * NQ * M_CH)   // 4096 gate entries

// Precomputed Rot gates: [layer][qubit][m][8] = (g00r,g00i,g01r,g01i,g10r,g10i,g11r,g11i)
__device__ float g_gates[NGATE * 8];
// Pooling partials: [b*16+slice][side][m] -> 2048*2*512 floats = 8 MB (L2-resident)
__device__ float g_part[B_SZ * NSLICE * 2 * M_CH];

// ---- Kernel P: streaming pooling partials (float4). CTA = (b, 2-row slice).
//      CTAs 0..31 additionally compute the 4096 Rot gates (hidden under the stream).
__global__ __launch_bounds__(128) void pool_kernel(const float* __restrict__ in,
                                                   const float* __restrict__ w) {
    const int bid = blockIdx.x;            // 0..2047
    const int t   = threadIdx.x;           // 0..127  (= m4, 4 channels each)

    // --- embedded gate construction (first 32 CTAs only) ---
    if (bid < 32) {
        int g_idx  = bid * 128 + t;        // 0..4095
        int m      = g_idx & (M_CH - 1);
        int q      = (g_idx >> 9) & 3;
        int layer  = g_idx >> 11;
        const float* wp = w + m * (DEPTH * NQ * 3) + layer * (NQ * 3) + q * 3;
        float phi = wp[0], theta = wp[1], omega = wp[2];
        float st, ct; sincosf(0.5f * theta,         &st, &ct);
        float sp, cp; sincosf(0.5f * (phi + omega), &sp, &cp);
        float sm, cm; sincosf(0.5f * (phi - omega), &sm, &cm);
        float* g = g_gates + (size_t)g_idx * 8;
        g[0] =  cp * ct;  g[1] = -sp * ct;
        g[2] = -cm * st;  g[3] = -sm * st;
        g[4] =  cm * st;  g[5] = -sm * st;
        g[6] =  cp * ct;  g[7] =  sp * ct;
    }

    const int b     = bid >> 4;
    const int slice = bid & (NSLICE - 1);
    const int row0  = slice * 2;

    const float4* base = (const float4*)in
                       + ((size_t)b * 1024 + (size_t)row0 * 32) * 128 + t;
    float4 sL = make_float4(0.f, 0.f, 0.f, 0.f);
    float4 sR = make_float4(0.f, 0.f, 0.f, 0.f);
    #pragma unroll
    for (int r = 0; r < 2; r++) {
        const float4* rp = base + (size_t)r * 32 * 128;
        #pragma unroll
        for (int c = 0; c < 16; c++) {
            float4 v = __ldg(rp + c * 128);
            sL.x += v.x; sL.y += v.y; sL.z += v.z; sL.w += v.w;
        }
        #pragma unroll
        for (int c = 16; c < 32; c++) {
            float4 v = __ldg(rp + c * 128);
            sR.x += v.x; sR.y += v.y; sR.z += v.z; sR.w += v.w;
        }
    }
    float4* p = (float4*)g_part + (size_t)bid * 256;   // 2 sides * 128 float4
    p[t]       = sL;
    p[128 + t] = sR;
}

// ---- Kernel S: reduce partials (L2-hot) + 4-qubit sim ----
__global__ __launch_bounds__(512) void sim_kernel(float* __restrict__ out) {
    const int b = blockIdx.x;
    const int m = threadIdx.x;

    const float* p = g_part + (size_t)b * (NSLICE * 2 * M_CH) + m;
    float a00 = 0.f, a01 = 0.f, a10 = 0.f, a11 = 0.f;
    #pragma unroll
    for (int s = 0; s < 8; s++) {
        a00 += p[s * 2 * M_CH];
        a01 += p[s * 2 * M_CH + M_CH];
    }
    #pragma unroll
    for (int s = 8; s < 16; s++) {
        a10 += p[s * 2 * M_CH];
        a11 += p[s * 2 * M_CH + M_CH];
    }

    const float PI = 3.14159265358979f;
    const float inv = 1.f / 256.f;
    float ang0 = tanhf(a00 * inv) * PI;
    float ang1 = tanhf(a01 * inv) * PI;
    float ang2 = tanhf(a10 * inv) * PI;
    float ang3 = tanhf(a11 * inv) * PI;

    float s0, c0, s1, c1, s2, c2, s3, c3;
    sincosf(0.5f * ang0, &s0, &c0);
    sincosf(0.5f * ang1, &s1, &c1);
    sincosf(0.5f * ang2, &s2, &c2);
    sincosf(0.5f * ang3, &s3, &c3);

    float re[16], im[16];
    {
        float p0[2] = {c0, s0}, p1[2] = {c1, s1}, p2[2] = {c2, s2}, p3[2] = {c3, s3};
        #pragma unroll
        for (int x = 0; x < 16; x++) {
            re[x] = p0[(x >> 3) & 1] * p1[(x >> 2) & 1] * p2[(x >> 1) & 1] * p3[x & 1];
            im[x] = 0.f;
        }
    }

    // 6-CNOT cascade composed: (a,b,c,d) -> (a, a^b, b^c, c^d); new[PERM[x]] = old[x]
    const int PERM[16] = {0, 1, 3, 2, 6, 7, 5, 4, 12, 13, 15, 14, 10, 11, 9, 8};

    #pragma unroll
    for (int layer = 0; layer < DEPTH; layer++) {
        #pragma unroll
        for (int q = 0; q < NQ; q++) {
            const float4* gp =
                (const float4*)(g_gates + ((size_t)((layer * NQ + q) * M_CH + m)) * 8);
            float4 gA = gp[0];
            float4 gB = gp[1];
            const int mask = 8 >> q;
            #pragma unroll
            for (int i = 0; i < 16; i++) {
                if (i & mask) continue;
                const int j = i | mask;
                float ar = re[i], ai = im[i], br = re[j], bi = im[j];
                re[i] = gA.x * ar - gA.y * ai + gA.z * br - gA.w * bi;
                im[i] = gA.x * ai + gA.y * ar + gA.z * bi + gA.w * br;
                re[j] = gB.x * ar - gB.y * ai + gB.z * br - gB.w * bi;
                im[j] = gB.x * ai + gB.y * ar + gB.z * bi + gB.w * br;
            }
        }
        float tr[16], ti[16];
        #pragma unroll
        for (int x = 0; x < 16; x++) { tr[PERM[x]] = re[x]; ti[PERM[x]] = im[x]; }
        #pragma unroll
        for (int x = 0; x < 16; x++) { re[x] = tr[x]; im[x] = ti[x]; }
    }

    float z = 0.f;
    #pragma unroll
    for (int x = 0; x < 8; x++)  z += re[x] * re[x] + im[x] * im[x];
    #pragma unroll
    for (int x = 8; x < 16; x++) z -= re[x] * re[x] + im[x] * im[x];

    out[(size_t)b * M_CH + m] = z;
}

extern "C" void kernel_launch(void* const* d_in, const int* in_sizes, int n_in,
                              void* d_out, int out_size) {
    const float* in = (const float*)d_in[0];
    const float* w  = (const float*)d_in[1];
    if (n_in >= 2 && in_sizes[0] < in_sizes[1]) {
        const float* t = in; in = w; w = t;
    }
    pool_kernel<<<B_SZ * NSLICE, 128>>>(in, w);
    sim_kernel<<<B_SZ, 512>>>((float*)d_out);
}

// round 6
// speedup vs baseline: 1.1173x; 1.0603x over previous
#include <cuda_runtime.h>
#include <math.h>

#define DEPTH 2
#define NQ 4
#define M_CH 512
#define B_SZ 128
#define NSLICE 16          // 2-row slices per image
#define NGATE (DEPTH * NQ * M_CH)   // 4096 gate entries

// Precomputed Rot gates: [step(layer*4+q)][m] x 8 floats = (g00r,g00i,g01r,g01i,g10r,g10i,g11r,g11i)
__device__ float g_gates[NGATE * 8];
// Pooling partials: [b*16+slice][side][m] -> 2048*2*512 floats = 8 MB (kept L2-resident)
__device__ float g_part[B_SZ * NSLICE * 2 * M_CH];

// ---- Kernel P: streaming pooling partials (float4, evict-first loads).
//      CTA = (b, 2-row slice). CTAs 0..31 additionally compute the 4096 Rot gates.
__global__ __launch_bounds__(128) void pool_kernel(const float* __restrict__ in,
                                                   const float* __restrict__ w) {
    const int bid = blockIdx.x;            // 0..2047
    const int t   = threadIdx.x;           // 0..127 (channel group, 4 channels)

    // --- embedded gate construction (first 32 CTAs only) ---
    if (bid < 32) {
        int g_idx  = bid * 128 + t;        // 0..4095
        int m      = g_idx & (M_CH - 1);
        int q      = (g_idx >> 9) & 3;
        int layer  = g_idx >> 11;
        const float* wp = w + m * (DEPTH * NQ * 3) + layer * (NQ * 3) + q * 3;
        float phi = wp[0], theta = wp[1], omega = wp[2];
        float st, ct; sincosf(0.5f * theta,         &st, &ct);
        float sp, cp; sincosf(0.5f * (phi + omega), &sp, &cp);
        float sm, cm; sincosf(0.5f * (phi - omega), &sm, &cm);
        // layout: [step][m] with step = layer*4+q  (sim reads float4 pairs coalesced on m)
        float* g = g_gates + ((size_t)(layer * NQ + q) * M_CH + m) * 8;
        g[0] =  cp * ct;  g[1] = -sp * ct;
        g[2] = -cm * st;  g[3] = -sm * st;
        g[4] =  cm * st;  g[5] = -sm * st;
        g[6] =  cp * ct;  g[7] =  sp * ct;
    }

    const int b     = bid >> 4;
    const int slice = bid & (NSLICE - 1);

    const float4* base = (const float4*)in
                       + ((size_t)b * 1024 + (size_t)slice * 64) * 128 + t;
    float4 sL = make_float4(0.f, 0.f, 0.f, 0.f);
    float4 sR = make_float4(0.f, 0.f, 0.f, 0.f);
    #pragma unroll
    for (int r = 0; r < 2; r++) {
        const float4* rp = base + (size_t)r * 32 * 128;
        #pragma unroll
        for (int c = 0; c < 16; c++) {
            float4 v = __ldcs(rp + c * 128);     // evict-first: don't churn L2
            sL.x += v.x; sL.y += v.y; sL.z += v.z; sL.w += v.w;
        }
        #pragma unroll
        for (int c = 16; c < 32; c++) {
            float4 v = __ldcs(rp + c * 128);
            sR.x += v.x; sR.y += v.y; sR.z += v.z; sR.w += v.w;
        }
    }
    float4* p = (float4*)g_part + (size_t)bid * 256;   // normal stores -> L2-resident
    p[t]       = sL;
    p[128 + t] = sR;
}

__device__ __forceinline__ float fast_tanh(float x) {
    // tanh(x) = 2/(1+e^-2x) - 1 ; plenty accurate for rel_err 1e-3 budget
    return __fdividef(2.f, 1.f + __expf(-2.f * x)) - 1.f;
}

// ---- Kernel S: reduce partials (L2-hot) + 4-qubit sim ----
__global__ __launch_bounds__(256) void sim_kernel(float* __restrict__ out) {
    const int b = blockIdx.x >> 1;                       // 0..127
    const int m = ((blockIdx.x & 1) << 8) + threadIdx.x; // 0..511

    // ---- partial reduction (16 independent coalesced loads) ----
    const float* p = g_part + (size_t)b * (NSLICE * 2 * M_CH) + m;
    float v[16];
    #pragma unroll
    for (int s = 0; s < 16; s++) v[s] = p[s * M_CH];     // [slice0 L,R, slice1 L,R, ...] halves
    // layout: index s = slice*2+side ; slices 0..7 are top rows, 8..15 bottom
    float a00 = 0.f, a01 = 0.f, a10 = 0.f, a11 = 0.f;
    #pragma unroll
    for (int s = 0; s < 8; s++)  { a00 += v[s * 2]; a01 += v[s * 2 + 1]; }
    float v2[16];
    const float* p2 = p + 8 * 2 * M_CH;
    #pragma unroll
    for (int s = 0; s < 16; s++) v2[s] = p2[s * M_CH];
    #pragma unroll
    for (int s = 0; s < 8; s++)  { a10 += v2[s * 2]; a11 += v2[s * 2 + 1]; }

    const float PI = 3.14159265358979f;
    const float inv = 1.f / 256.f;
    float ang0 = fast_tanh(a00 * inv) * PI;
    float ang1 = fast_tanh(a01 * inv) * PI;
    float ang2 = fast_tanh(a10 * inv) * PI;
    float ang3 = fast_tanh(a11 * inv) * PI;

    float s0, c0, s1, c1, s2, c2, s3, c3;
    __sincosf(0.5f * ang0, &s0, &c0);     // |arg| <= pi/2: fast path is accurate
    __sincosf(0.5f * ang1, &s1, &c1);
    __sincosf(0.5f * ang2, &s2, &c2);
    __sincosf(0.5f * ang3, &s3, &c3);

    float re[16], im[16];
    {
        float p0[2] = {c0, s0}, p1[2] = {c1, s1}, p2_[2] = {c2, s2}, p3[2] = {c3, s3};
        #pragma unroll
        for (int x = 0; x < 16; x++) {
            re[x] = p0[(x >> 3) & 1] * p1[(x >> 2) & 1] * p2_[(x >> 1) & 1] * p3[x & 1];
            im[x] = 0.f;
        }
    }

    // 6-CNOT cascade composed: (a,b,c,d) -> (a, a^b, b^c, c^d); new[PERM[x]] = old[x]
    const int PERM[16] = {0, 1, 3, 2, 6, 7, 5, 4, 12, 13, 15, 14, 10, 11, 9, 8};

    // gates: [step][m] -> float4 pair; software-pipeline the loads
    const float4* gp0 = (const float4*)g_gates + (size_t)m * 2;
    float4 gA = __ldg(gp0);
    float4 gB = __ldg(gp0 + 1);

    #pragma unroll
    for (int step = 0; step < DEPTH * NQ; step++) {
        float4 nA, nB;
        if (step < DEPTH * NQ - 1) {
            const float4* gn = gp0 + (size_t)(step + 1) * M_CH * 2;
            nA = __ldg(gn);
            nB = __ldg(gn + 1);
        }
        const int q = step & 3;
        const int mask = 8 >> q;
        #pragma unroll
        for (int i = 0; i < 16; i++) {
            if (i & mask) continue;
            const int j = i | mask;
            float ar = re[i], ai = im[i], br = re[j], bi = im[j];
            re[i] = gA.x * ar - gA.y * ai + gA.z * br - gA.w * bi;
            im[i] = gA.x * ai + gA.y * ar + gA.z * bi + gA.w * br;
            re[j] = gB.x * ar - gB.y * ai + gB.z * br - gB.w * bi;
            im[j] = gB.x * ai + gB.y * ar + gB.z * bi + gB.w * br;
        }
        if (q == 3) {   // end of a layer: apply CNOT cascade permutation
            float tr[16], ti[16];
            #pragma unroll
            for (int x = 0; x < 16; x++) { tr[PERM[x]] = re[x]; ti[PERM[x]] = im[x]; }
            #pragma unroll
            for (int x = 0; x < 16; x++) { re[x] = tr[x]; im[x] = ti[x]; }
        }
        gA = nA; gB = nB;
    }

    float z = 0.f;
    #pragma unroll
    for (int x = 0; x < 8; x++)  z += re[x] * re[x] + im[x] * im[x];
    #pragma unroll
    for (int x = 8; x < 16; x++) z -= re[x] * re[x] + im[x] * im[x];

    out[(size_t)b * M_CH + m] = z;
}

extern "C" void kernel_launch(void* const* d_in, const int* in_sizes, int n_in,
                              void* d_out, int out_size) {
    const float* in = (const float*)d_in[0];
    const float* w  = (const float*)d_in[1];
    if (n_in >= 2 && in_sizes[0] < in_sizes[1]) {
        const float* t = in; in = w; w = t;
    }
    pool_kernel<<<B_SZ * NSLICE, 128>>>(in, w);
    sim_kernel<<<B_SZ * 2, 256>>>((float*)d_out);
}

// round 7
// speedup vs baseline: 1.1180x; 1.0006x over previous
#include <cuda_runtime.h>
#include <math.h>

#define DEPTH 2
#define NQ 4
#define M_CH 512
#define B_SZ 128
#define NSL 8              // 4-row slices per image
#define NGATE (DEPTH * NQ * M_CH)   // 4096 gate entries

// Precomputed Rot gates: [step(layer*4+q)][m] x 8 floats
__device__ float g_gates[NGATE * 8];
// Pooling partials: [b][slice][side][m] -> 128*8*2*512 floats = 2 MB
__device__ float g_part[B_SZ * NSL * 2 * M_CH];

// ---- Kernel P: streaming pool. CTA = (b, 4-row slice), 512 threads.
//      thread = (row-in-slice rs = t>>7, channel-group m4 = t&127)
//      CTAs 0..7 additionally compute the 4096 Rot gates.
__global__ __launch_bounds__(512) void pool_kernel(const float* __restrict__ in,
                                                   const float* __restrict__ w) {
    const int bid = blockIdx.x;            // 0..1023
    const int t   = threadIdx.x;           // 0..511

    // --- embedded gate construction (first 8 CTAs, one gate per thread) ---
    if (bid < 8) {
        int g_idx  = bid * 512 + t;        // 0..4095
        int m      = g_idx & (M_CH - 1);
        int q      = (g_idx >> 9) & 3;
        int layer  = g_idx >> 11;
        const float* wp = w + m * (DEPTH * NQ * 3) + layer * (NQ * 3) + q * 3;
        float phi = wp[0], theta = wp[1], omega = wp[2];
        float st, ct; sincosf(0.5f * theta,         &st, &ct);
        float sp, cp; sincosf(0.5f * (phi + omega), &sp, &cp);
        float sm, cm; sincosf(0.5f * (phi - omega), &sm, &cm);
        float* g = g_gates + ((size_t)(layer * NQ + q) * M_CH + m) * 8;
        g[0] =  cp * ct;  g[1] = -sp * ct;
        g[2] = -cm * st;  g[3] = -sm * st;
        g[4] =  cm * st;  g[5] = -sm * st;
        g[6] =  cp * ct;  g[7] =  sp * ct;
    }

    const int b     = bid >> 3;
    const int slice = bid & (NSL - 1);
    const int rs    = t >> 7;              // row within slice (0..3)
    const int m4    = t & 127;             // channel group (4 channels)
    const int row   = slice * 4 + rs;

    const float4* rp = (const float4*)in
                     + ((size_t)b * 1024 + (size_t)row * 32) * 128 + m4;
    float4 sL = make_float4(0.f, 0.f, 0.f, 0.f);
    float4 sR = make_float4(0.f, 0.f, 0.f, 0.f);
    #pragma unroll
    for (int c = 0; c < 16; c++) {
        float4 v = __ldcs(rp + c * 128);     // evict-first streaming
        sL.x += v.x; sL.y += v.y; sL.z += v.z; sL.w += v.w;
    }
    #pragma unroll
    for (int c = 16; c < 32; c++) {
        float4 v = __ldcs(rp + c * 128);
        sR.x += v.x; sR.y += v.y; sR.z += v.z; sR.w += v.w;
    }

    // --- in-CTA reduction over the 4 rows ---
    __shared__ float4 red[512 * 2];
    red[t * 2]     = sL;
    red[t * 2 + 1] = sR;
    __syncthreads();
    if (t < 256) {
        float4 a = red[t * 2],     b4 = red[(t + 256) * 2];
        float4 c = red[t * 2 + 1], d4 = red[(t + 256) * 2 + 1];
        a.x += b4.x; a.y += b4.y; a.z += b4.z; a.w += b4.w;
        c.x += d4.x; c.y += d4.y; c.z += d4.z; c.w += d4.w;
        red[t * 2]     = a;
        red[t * 2 + 1] = c;
    }
    __syncthreads();
    if (t < 128) {
        float4 a = red[t * 2],     b4 = red[(t + 128) * 2];
        float4 c = red[t * 2 + 1], d4 = red[(t + 128) * 2 + 1];
        a.x += b4.x; a.y += b4.y; a.z += b4.z; a.w += b4.w;
        c.x += d4.x; c.y += d4.y; c.z += d4.z; c.w += d4.w;
        float4* p = (float4*)g_part + ((size_t)(b * NSL + slice) * 2) * 128 + t;
        p[0]   = a;      // side L
        p[128] = c;      // side R
    }
}

__device__ __forceinline__ float fast_tanh(float x) {
    return __fdividef(2.f, 1.f + __expf(-2.f * x)) - 1.f;
}

// ---- Kernel S: reduce partials (2 MB) + 4-qubit sim ----
__global__ __launch_bounds__(256) void sim_kernel(float* __restrict__ out) {
    const int b = blockIdx.x >> 1;                       // 0..127
    const int m = ((blockIdx.x & 1) << 8) + threadIdx.x; // 0..511

    // partials: [b][slice(8)][side(2)][m]; slices 0..3 top half, 4..7 bottom
    const float* p = g_part + (size_t)b * (NSL * 2 * M_CH) + m;
    float v[16];
    #pragma unroll
    for (int s = 0; s < 16; s++) v[s] = p[s * M_CH];
    float a00 = 0.f, a01 = 0.f, a10 = 0.f, a11 = 0.f;
    #pragma unroll
    for (int s = 0; s < 4; s++) { a00 += v[s * 2];     a01 += v[s * 2 + 1]; }
    #pragma unroll
    for (int s = 4; s < 8; s++) { a10 += v[s * 2];     a11 += v[s * 2 + 1]; }

    const float PI = 3.14159265358979f;
    const float inv = 1.f / 256.f;
    float ang0 = fast_tanh(a00 * inv) * PI;
    float ang1 = fast_tanh(a01 * inv) * PI;
    float ang2 = fast_tanh(a10 * inv) * PI;
    float ang3 = fast_tanh(a11 * inv) * PI;

    float s0, c0, s1, c1, s2, c2, s3, c3;
    __sincosf(0.5f * ang0, &s0, &c0);
    __sincosf(0.5f * ang1, &s1, &c1);
    __sincosf(0.5f * ang2, &s2, &c2);
    __sincosf(0.5f * ang3, &s3, &c3);

    float re[16], im[16];
    {
        float p0[2] = {c0, s0}, p1[2] = {c1, s1}, p2_[2] = {c2, s2}, p3[2] = {c3, s3};
        #pragma unroll
        for (int x = 0; x < 16; x++) {
            re[x] = p0[(x >> 3) & 1] * p1[(x >> 2) & 1] * p2_[(x >> 1) & 1] * p3[x & 1];
            im[x] = 0.f;
        }
    }

    // 6-CNOT cascade composed: (a,b,c,d) -> (a, a^b, b^c, c^d); new[PERM[x]] = old[x]
    const int PERM[16] = {0, 1, 3, 2, 6, 7, 5, 4, 12, 13, 15, 14, 10, 11, 9, 8};

    const float4* gp0 = (const float4*)g_gates + (size_t)m * 2;
    float4 gA = __ldg(gp0);
    float4 gB = __ldg(gp0 + 1);

    #pragma unroll
    for (int step = 0; step < DEPTH * NQ; step++) {
        float4 nA, nB;
        if (step < DEPTH * NQ - 1) {
            const float4* gn = gp0 + (size_t)(step + 1) * M_CH * 2;
            nA = __ldg(gn);
            nB = __ldg(gn + 1);
        }
        const int q = step & 3;
        const int mask = 8 >> q;
        #pragma unroll
        for (int i = 0; i < 16; i++) {
            if (i & mask) continue;
            const int j = i | mask;
            float ar = re[i], ai = im[i], br = re[j], bi = im[j];
            re[i] = gA.x * ar - gA.y * ai + gA.z * br - gA.w * bi;
            im[i] = gA.x * ai + gA.y * ar + gA.z * bi + gA.w * br;
            re[j] = gB.x * ar - gB.y * ai + gB.z * br - gB.w * bi;
            im[j] = gB.x * ai + gB.y * ar + gB.z * bi + gB.w * br;
        }
        if (q == 3) {
            float tr[16], ti[16];
            #pragma unroll
            for (int x = 0; x < 16; x++) { tr[PERM[x]] = re[x]; ti[PERM[x]] = im[x]; }
            #pragma unroll
            for (int x = 0; x < 16; x++) { re[x] = tr[x]; im[x] = ti[x]; }
        }
        gA = nA; gB = nB;
    }

    float z = 0.f;
    #pragma unroll
    for (int x = 0; x < 8; x++)  z += re[x] * re[x] + im[x] * im[x];
    #pragma unroll
    for (int x = 8; x < 16; x++) z -= re[x] * re[x] + im[x] * im[x];

    out[(size_t)b * M_CH + m] = z;
}

extern "C" void kernel_launch(void* const* d_in, const int* in_sizes, int n_in,
                              void* d_out, int out_size) {
    const float* in = (const float*)d_in[0];
    const float* w  = (const float*)d_in[1];
    if (n_in >= 2 && in_sizes[0] < in_sizes[1]) {
        const float* t = in; in = w; w = t;
    }
    pool_kernel<<<B_SZ * NSL, 512>>>(in, w);
    sim_kernel<<<B_SZ * 2, 256>>>((float*)d_out);
}